// round 6
// baseline (speedup 1.0000x reference)
#include <cuda_runtime.h>
#include <stdint.h>

// out[i, :] = W[idx[i], :]   idx:[32768] int32, W:[8192,512] f32, out:[32768,512] f32
// Flat gather over float4 lanes. 4,194,304 vectors; 256 thr * 8 = 2048 vec/CTA; grid = 2048.
// Per-thread: 8 independent gathers front-batched (MLP=8).
//   table loads via __ldcg (L2-only; no L1 reuse exists for gathered rows)
//   stores via __stcs   (streaming / evict-first; protects table's L2 residency)
// Row decomposition strength-reduced: per-thread row stride is exactly +2
// (256 threads per step / 128 float4 per row), lane-in-row invariant.

static constexpr int E_DIM    = 512;
static constexpr int VEC_ROW  = E_DIM / 4;   // 128 float4 per row
static constexpr int THREADS  = 256;
static constexpr int UNROLL   = 8;

__global__ void __launch_bounds__(THREADS)
gather_rows_kernel(const int* __restrict__ idx,
                   const float4* __restrict__ table,   // [8192, 128] float4
                   float4* __restrict__ out)           // [32768, 128] float4
{
    const int base  = (blockIdx.x * THREADS) * UNROLL + threadIdx.x;
    const int row0  = base >> 7;              // starting row for u=0
    const int t     = base & (VEC_ROW - 1);   // lane-in-row, invariant across u

    float4 v[UNROLL];

    // Front-batched independent index + gather loads (MLP = 8)
    #pragma unroll
    for (int u = 0; u < UNROLL; ++u) {
        const int row = row0 + 2 * u;                       // +256 vec == +2 rows
        const int src = __ldg(&idx[row]);                   // tiny, L1-hot
        v[u] = __ldcg(&table[(size_t)src * VEC_ROW + t]);   // L2-only gather
    }

    #pragma unroll
    for (int u = 0; u < UNROLL; ++u) {
        __stcs(&out[base + u * THREADS], v[u]);             // streaming store
    }
}

extern "C" void kernel_launch(void* const* d_in, const int* in_sizes, int n_in,
                              void* d_out, int out_size)
{
    const int*    idx   = (const int*)d_in[0];      // min_encoding_indices [32768]
    const float4* table = (const float4*)d_in[1];   // embedding_weight [8192,512]
    float4*       out   = (float4*)d_out;           // [32,1024,512] f32

    const int n_rows    = in_sizes[0];              // 32768
    const int total_vec = n_rows * VEC_ROW;         // 4,194,304
    const int per_cta   = THREADS * UNROLL;         // 2048
    const int grid      = total_vec / per_cta;      // 2048 (exact)

    gather_rows_kernel<<<grid, THREADS>>>(idx, table, out);
}

// round 7
// speedup vs baseline: 1.0098x; 1.0098x over previous
#include <cuda_runtime.h>
#include <stdint.h>

// out[i,:] = W[idx[i],:]  idx:[32768] i32, W:[8192,512] f32, out:[32768,512] f32
// Bulk-async (TMA-path) gather: each row = 2 KB contiguous. Per CTA: 16 rows,
// 8 smem stages, 4 outstanding bulk loads; stores via bulk_group smem->global.
// Single driver thread per CTA; data never touches registers/L1tex.

static constexpr int ROW_BYTES    = 2048;
static constexpr int STAGES       = 8;
static constexpr int DEPTH        = 4;    // outstanding g->s loads
static constexpr int ROWS_PER_CTA = 16;

__device__ __forceinline__ uint32_t smem_u32(const void* p) {
    return (uint32_t)__cvta_generic_to_shared(p);
}

__device__ __forceinline__ void bulk_load_row(uint32_t dst, const char* src, uint32_t bar) {
    asm volatile("mbarrier.arrive.expect_tx.shared.b64 _, [%0], %1;"
                 :: "r"(bar), "r"((uint32_t)ROW_BYTES) : "memory");
    asm volatile("cp.async.bulk.shared::cluster.global.mbarrier::complete_tx::bytes "
                 "[%0], [%1], %2, [%3];"
                 :: "r"(dst), "l"(src), "r"((uint32_t)ROW_BYTES), "r"(bar) : "memory");
}

__device__ __forceinline__ void wait_full(uint32_t bar, uint32_t parity) {
    uint32_t done;
    do {
        asm volatile(
            "{ .reg .pred p;\n\t"
            "mbarrier.try_wait.parity.acquire.cta.shared::cta.b64 p, [%1], %2, 0x989680;\n\t"
            "selp.b32 %0, 1, 0, p; }"
            : "=r"(done) : "r"(bar), "r"(parity) : "memory");
    } while (!done);
}

__global__ void __launch_bounds__(32)
gather_tma_kernel(const int* __restrict__ idx,
                  const char* __restrict__ table,
                  char* __restrict__ out)
{
    __shared__ alignas(128) char buf[STAGES][ROW_BYTES];
    __shared__ alignas(8) uint64_t mbar[STAGES];

    if (threadIdx.x != 0) return;   // single driver thread

    #pragma unroll
    for (int s = 0; s < STAGES; ++s) {
        asm volatile("mbarrier.init.shared.b64 [%0], 1;" :: "r"(smem_u32(&mbar[s])));
    }
    asm volatile("fence.proxy.async.shared::cta;" ::: "memory");

    const int rowBase = blockIdx.x * ROWS_PER_CTA;

    int src[ROWS_PER_CTA];
    #pragma unroll
    for (int i = 0; i < ROWS_PER_CTA; ++i) src[i] = __ldg(&idx[rowBase + i]);

    // Prologue: fill load pipeline DEPTH deep
    #pragma unroll
    for (int i = 0; i < DEPTH; ++i) {
        const int s = i & (STAGES - 1);
        bulk_load_row(smem_u32(buf[s]), table + (size_t)src[i] * ROW_BYTES,
                      smem_u32(&mbar[s]));
    }

    #pragma unroll
    for (int i = 0; i < ROWS_PER_CTA; ++i) {
        const int s       = i & (STAGES - 1);
        const uint32_t ph = (i >> 3) & 1;          // stage s serves rows s, s+8

        wait_full(smem_u32(&mbar[s]), ph);

        // smem -> global bulk store (async proxy reads TMA-written smem: no fence needed)
        asm volatile("cp.async.bulk.global.shared::cta.bulk_group [%0], [%1], %2;"
                     :: "l"(out + (size_t)(rowBase + i) * ROW_BYTES),
                        "r"(smem_u32(buf[s])), "r"((uint32_t)ROW_BYTES) : "memory");
        asm volatile("cp.async.bulk.commit_group;" ::: "memory");

        const int nxt = i + DEPTH;
        if (nxt < ROWS_PER_CTA) {
            // Stage nxt%8's previous store is 4 groups old; <=3 pending ensures it
            // has been read out of smem (groups retire in order).
            asm volatile("cp.async.bulk.wait_group.read 3;" ::: "memory");
            const int s2 = nxt & (STAGES - 1);
            bulk_load_row(smem_u32(buf[s2]), table + (size_t)src[nxt] * ROW_BYTES,
                          smem_u32(&mbar[s2]));
        }
    }

    // All stores globally committed before CTA exit
    asm volatile("cp.async.bulk.wait_group 0;" ::: "memory");
}

extern "C" void kernel_launch(void* const* d_in, const int* in_sizes, int n_in,
                              void* d_out, int out_size)
{
    const int*  idx   = (const int*)d_in[0];     // [32768]
    const char* table = (const char*)d_in[1];    // [8192,512] f32 = 8192 x 2KB
    char*       out   = (char*)d_out;            // [32768,512] f32

    const int n_rows = in_sizes[0];              // 32768
    const int grid   = n_rows / ROWS_PER_CTA;    // 2048 (exact)

    gather_tma_kernel<<<grid, 32>>>(idx, table, out);
}